// round 14
// baseline (speedup 1.0000x reference)
#include <cuda_runtime.h>
#include <cuda_fp16.h>
#include <cstdint>
#include <math.h>

#define H 1024
#define IDIM 4096
#define NE 8
#define T_TOK 8192
#define NSLOT (2 * T_TOK)

// ---------------- device scratch ----------------
__device__ int    g_count[NE];
__device__ int    g_base[NE];
__device__ int    g_tok[NE * T_TOK];
__device__ float  g_wt[NE * T_TOK];
__device__ float  g_probs[T_TOK * NE];
__device__ __half g_h[(size_t)(NSLOT + 128) * IDIM];     // hidden acts (fp16)
__device__ __half g_xh[(size_t)T_TOK * H];               // x in fp16
__device__ __half g_w1h[(size_t)NE * 2 * IDIM * H];      // gate_up_w fp16
__device__ __half g_w2h[(size_t)NE * H * IDIM];          // down_w fp16

// ---------------- helpers ----------------
__device__ __forceinline__ uint32_t h2pack(float a, float b) {
    __half2 h = __floats2half2_rn(a, b);
    return *(uint32_t*)&h;
}
__device__ __forceinline__ uint2 cvt4h(float4 v) {
    return make_uint2(h2pack(v.x, v.y), h2pack(v.z, v.w));
}
__device__ __forceinline__ uint32_t smem_u32(const void* p) {
    uint32_t a;
    asm("{ .reg .u64 t; cvta.to.shared.u64 t, %1; cvt.u32.u64 %0, t; }" : "=r"(a) : "l"(p));
    return a;
}
__device__ __forceinline__ void cp16(uint32_t dst, const void* src) {
    asm volatile("cp.async.cg.shared.global [%0], [%1], 16;" :: "r"(dst), "l"(src));
}
#define CP_COMMIT() asm volatile("cp.async.commit_group;" ::: "memory")
#define CP_WAIT0()  asm volatile("cp.async.wait_group 0;" ::: "memory")

__device__ __forceinline__ void mma_f16(float* d, const unsigned* a, const unsigned* b) {
    asm volatile(
        "mma.sync.aligned.m16n8k16.row.col.f32.f16.f16.f32 "
        "{%0,%1,%2,%3}, {%4,%5,%6,%7}, {%8,%9}, {%0,%1,%2,%3};\n"
        : "+f"(d[0]), "+f"(d[1]), "+f"(d[2]), "+f"(d[3])
        : "r"(a[0]), "r"(a[1]), "r"(a[2]), "r"(a[3]), "r"(b[0]), "r"(b[1]));
}
__device__ __forceinline__ void ldsm_x4(unsigned* r, uint32_t addr) {
    asm volatile("ldmatrix.sync.aligned.m8n8.x4.shared.b16 {%0,%1,%2,%3}, [%4];"
                 : "=r"(r[0]), "=r"(r[1]), "=r"(r[2]), "=r"(r[3]) : "r"(addr));
}

// ---------------- zero / init ----------------
__global__ void zero_out_kernel(float* out, int n) {
    int i = blockIdx.x * blockDim.x + threadIdx.x;
    int stride = gridDim.x * blockDim.x;
    if (i < NE) g_count[i] = 0;
    for (; i < n; i += stride) out[i] = 0.0f;
}

// ---------------- fp32 -> fp16 conversion ----------------
__global__ void cvt_f2h_kernel(const float4* __restrict__ src, uint2* __restrict__ dst,
                               size_t n4) {
    size_t i = (size_t)blockIdx.x * blockDim.x + threadIdx.x;
    size_t stride = (size_t)gridDim.x * blockDim.x;
    for (; i < n4; i += stride) dst[i] = cvt4h(src[i]);
}

// ---------------- gating: logits, softmax, top-2, routing ----------------
__global__ __launch_bounds__(256) void gating_kernel(const float* __restrict__ x,
                                                     const float* __restrict__ gw) {
    __shared__ float sgw[NE * H];
    for (int i = threadIdx.x; i < NE * H; i += blockDim.x) sgw[i] = gw[i];
    __syncthreads();

    int warp = threadIdx.x >> 5, lane = threadIdx.x & 31;
    int t = blockIdx.x * 8 + warp;
    const float* xr = x + (size_t)t * H;

    float acc[NE];
#pragma unroll
    for (int e = 0; e < NE; e++) acc[e] = 0.0f;
    for (int k = lane; k < H; k += 32) {
        float xv = xr[k];
#pragma unroll
        for (int e = 0; e < NE; e++) acc[e] += xv * sgw[e * H + k];
    }
#pragma unroll
    for (int e = 0; e < NE; e++)
#pragma unroll
        for (int off = 16; off; off >>= 1)
            acc[e] += __shfl_xor_sync(0xffffffffu, acc[e], off);

    if (lane == 0) {
        float mx = acc[0];
#pragma unroll
        for (int e = 1; e < NE; e++) mx = fmaxf(mx, acc[e]);
        float p[NE], s = 0.0f;
#pragma unroll
        for (int e = 0; e < NE; e++) { p[e] = expf(acc[e] - mx); s += p[e]; }
        float inv = 1.0f / s;
#pragma unroll
        for (int e = 0; e < NE; e++) { p[e] *= inv; g_probs[t * NE + e] = p[e]; }

        int b0 = 0;
#pragma unroll
        for (int e = 1; e < NE; e++) if (p[e] > p[b0]) b0 = e;
        int b1 = (b0 == 0) ? 1 : 0;
#pragma unroll
        for (int e = 0; e < NE; e++) if (e != b0 && p[e] > p[b1]) b1 = e;

        float d = 1.0f / (p[b0] + p[b1] + 1e-9f);
        int pos0 = atomicAdd(&g_count[b0], 1);
        g_tok[b0 * T_TOK + pos0] = t;
        g_wt[b0 * T_TOK + pos0] = p[b0] * d;
        int pos1 = atomicAdd(&g_count[b1], 1);
        g_tok[b1 * T_TOK + pos1] = t;
        g_wt[b1 * T_TOK + pos1] = p[b1] * d;
    }
}

// ---------------- prefix scan + aux loss ----------------
__global__ void scan_aux_kernel(float* out) {
    __shared__ float red[256];
    __shared__ float imp[NE];
    float s[NE];
#pragma unroll
    for (int e = 0; e < NE; e++) s[e] = 0.0f;
    for (int i = threadIdx.x; i < T_TOK; i += 256)
#pragma unroll
        for (int e = 0; e < NE; e++) s[e] += g_probs[i * NE + e];
    for (int e = 0; e < NE; e++) {
        red[threadIdx.x] = s[e];
        __syncthreads();
        for (int off = 128; off; off >>= 1) {
            if (threadIdx.x < off) red[threadIdx.x] += red[threadIdx.x + off];
            __syncthreads();
        }
        if (threadIdx.x == 0) imp[e] = red[0];
        __syncthreads();
    }
    if (threadIdx.x == 0) {
        int b = 0;
        float aux = 0.0f;
        for (int e = 0; e < NE; e++) {
            g_base[e] = b;
            b += g_count[e];
            float usage = (float)g_count[e] / ((float)(T_TOK * 2) + 1e-9f);
            aux += usage * (imp[e] / (float)T_TOK);
        }
        out[(size_t)T_TOK * H] = fminf(aux * (float)NE * 0.01f, 1.0f);
    }
}

// ---------------- GEMM tiling constants ----------------
#define BK 32
#define KS2 40     // half stride per smem row (80B): LDSM phases hit all 32 banks
#define NSTG 4     // 4 x BK32 stages used as two 64-K pairs

// ---------------- GEMM1: h = silu(x@Wg^T) * (x@Wu^T) ----------------
#define BM1 128
#define BN1 64
#define G1_STGH ((BM1 + 2 * BN1) * KS2)           // 10240 halves / stage
#define G1_SMEM (512 + NSTG * G1_STGH * 2)        // 82432 B

__global__ __launch_bounds__(256, 2) void gemm1_kernel(const __half* __restrict__ xh,
                                                       const __half* __restrict__ w1h) {
    int e = blockIdx.z;
    int cnt = g_count[e];
    int m0 = blockIdx.x * BM1;
    if (m0 >= cnt) return;
    int n0 = blockIdx.y * BN1;

    extern __shared__ __align__(16) char smraw[];
    int* stok = (int*)smraw;
    __half* stg = (__half*)(smraw + 512);
    uint32_t stg_b = smem_u32(stg);

    int tid = threadIdx.x, warp = tid >> 5, lane = tid & 31;
    int wm = warp >> 1, wn = warp & 1;

    if (tid < BM1) {
        int p = m0 + tid;
        stok[tid] = (p < cnt) ? g_tok[e * T_TOK + p] : 0;
    }
    __syncthreads();

    // per-thread cp.async plan: 4 x 16B chunks / stage
    const __half* srcb[4];
    uint32_t dsto[4];
#pragma unroll
    for (int t = 0; t < 4; t++) {
        int idx = tid + 256 * t;
        if (idx < 512) {
            int r = idx >> 2, c = idx & 3;
            srcb[t] = xh + (size_t)stok[r] * H + c * 8;
            dsto[t] = (r * KS2 + c * 8) * 2;
        } else if (idx < 768) {
            int j = idx - 512;
            int r = j >> 2, c = j & 3;
            srcb[t] = w1h + (size_t)e * 2 * IDIM * H + (size_t)(n0 + r) * H + c * 8;
            dsto[t] = ((BM1 + r) * KS2 + c * 8) * 2;
        } else {
            int j = idx - 768;
            int r = j >> 2, c = j & 3;
            srcb[t] = w1h + (size_t)e * 2 * IDIM * H + (size_t)(IDIM + n0 + r) * H + c * 8;
            dsto[t] = ((BM1 + BN1 + r) * KS2 + c * 8) * 2;
        }
    }

    // ldmatrix half-offsets (within a stage)
    uint32_t offA[2], offBg[2], offBu[2];
#pragma unroll
    for (int mf = 0; mf < 2; mf++)
        offA[mf] = (uint32_t)((wm * 32 + mf * 16 + (lane & 7) + ((lane >> 3) & 1) * 8) * KS2
                              + ((lane >> 4) & 1) * 8);
#pragma unroll
    for (int p = 0; p < 2; p++) {
        offBg[p] = (uint32_t)((BM1 + wn * 32 + p * 16 + (lane & 7) + ((lane >> 4) & 1) * 8) * KS2
                              + ((lane >> 3) & 1) * 8);
        offBu[p] = offBg[p] + BN1 * KS2;
    }

    const int NIT = (H / BK) / 2;  // 16 pair-iterations (64 K each)
    // prologue: pair 0 (stages 0,1 <- k-slabs 0,1), one commit group
#pragma unroll
    for (int s = 0; s < 2; s++) {
        uint32_t db = stg_b + s * G1_STGH * 2;
#pragma unroll
        for (int t = 0; t < 4; t++) cp16(db + dsto[t], srcb[t] + s * BK);
    }
    CP_COMMIT();

    float accg[2][4][4], accu[2][4][4];
#pragma unroll
    for (int a = 0; a < 2; a++)
#pragma unroll
        for (int b = 0; b < 4; b++)
#pragma unroll
            for (int c = 0; c < 4; c++) { accg[a][b][c] = 0.0f; accu[a][b][c] = 0.0f; }

    for (int it = 0; it < NIT; it++) {
        CP_WAIT0();
        __syncthreads();
        if (it + 1 < NIT) {
            int pp = (it + 1) & 1;  // opposite pair, computed at it-1, freed by the sync
#pragma unroll
            for (int s = 0; s < 2; s++) {
                uint32_t db = stg_b + (2 * pp + s) * G1_STGH * 2;
                int kslab = 2 * (it + 1) + s;
#pragma unroll
                for (int t = 0; t < 4; t++) cp16(db + dsto[t], srcb[t] + kslab * BK);
            }
            CP_COMMIT();
        }
        int cp = it & 1;
#pragma unroll
        for (int s = 0; s < 2; s++) {
            uint32_t stage_b = stg_b + (2 * cp + s) * G1_STGH * 2;
#pragma unroll
            for (int ks = 0; ks < 2; ks++) {
                uint32_t kb = stage_b + ks * 32;  // ks*16 halves
                unsigned a[2][4], bg[4][2], bu[4][2];
                ldsm_x4(a[0], kb + offA[0] * 2);
                ldsm_x4(a[1], kb + offA[1] * 2);
                ldsm_x4(&bg[0][0], kb + offBg[0] * 2);
                ldsm_x4(&bg[2][0], kb + offBg[1] * 2);
                ldsm_x4(&bu[0][0], kb + offBu[0] * 2);
                ldsm_x4(&bu[2][0], kb + offBu[1] * 2);
#pragma unroll
                for (int mf = 0; mf < 2; mf++)
#pragma unroll
                    for (int nf = 0; nf < 4; nf++) {
                        mma_f16(accg[mf][nf], a[mf], bg[nf]);
                        mma_f16(accu[mf][nf], a[mf], bu[nf]);
                    }
            }
        }
    }
    __syncthreads();

    // epilogue: silu(g)*u -> fp16, stage through smem (stride 72 halves)
    int g4 = lane >> 2, tig = lane & 3;
    __half* Hs = stg;
#pragma unroll
    for (int mf = 0; mf < 2; mf++)
#pragma unroll
        for (int nf = 0; nf < 4; nf++)
#pragma unroll
            for (int hh = 0; hh < 2; hh++) {
                int row = wm * 32 + mf * 16 + g4 + hh * 8;
                int col = wn * 32 + nf * 8 + tig * 2;
                float gv0 = accg[mf][nf][hh * 2 + 0], uv0 = accu[mf][nf][hh * 2 + 0];
                float gv1 = accg[mf][nf][hh * 2 + 1], uv1 = accu[mf][nf][hh * 2 + 1];
                float h0 = gv0 / (1.0f + __expf(-gv0)) * uv0;
                float h1 = gv1 / (1.0f + __expf(-gv1)) * uv1;
                *(uint32_t*)&Hs[row * 72 + col] = h2pack(h0, h1);
            }
    __syncthreads();

    int mybase = g_base[e];
#pragma unroll
    for (int t = 0; t < 4; t++) {
        int idx = tid + t * 256;
        int r = idx >> 3, c8 = idx & 7;
        if (m0 + r < cnt) {
            uint4 v = *(uint4*)&Hs[r * 72 + c8 * 8];
            *(uint4*)&g_h[(size_t)(mybase + m0 + r) * IDIM + n0 + c8 * 8] = v;
        }
    }
}

// ---------------- GEMM2: out[tok] += w * (h @ W2^T) ----------------
#define BM2 128
#define BN2 128
#define G2_STGH ((BM2 + BN2) * KS2)          // 10240 halves / stage
#define G2_SMEM (NSTG * G2_STGH * 2)         // 81920 B

__global__ __launch_bounds__(256, 2) void gemm2_kernel(const __half* __restrict__ w2h,
                                                       float* __restrict__ out) {
    int e = blockIdx.z;
    int cnt = g_count[e];
    int m0 = blockIdx.x * BM2;
    if (m0 >= cnt) return;
    int n0 = blockIdx.y * BN2;
    int base = g_base[e];

    extern __shared__ __align__(16) char smraw[];
    __half* stg = (__half*)smraw;
    uint32_t stg_b = smem_u32(stg);

    int tid = threadIdx.x, warp = tid >> 5, lane = tid & 31;
    int wm = warp >> 1, wn = warp & 1;

    const __half* Ab = g_h + (size_t)(base + m0) * IDIM;

    const __half* srcb[4];
    uint32_t dsto[4];
#pragma unroll
    for (int t = 0; t < 4; t++) {
        int idx = tid + 256 * t;
        if (idx < 512) {
            int r = idx >> 2, c = idx & 3;
            srcb[t] = Ab + (size_t)r * IDIM + c * 8;
            dsto[t] = (r * KS2 + c * 8) * 2;
        } else {
            int j = idx - 512;
            int r = j >> 2, c = j & 3;
            srcb[t] = w2h + ((size_t)e * H + n0 + r) * IDIM + c * 8;
            dsto[t] = ((BM2 + r) * KS2 + c * 8) * 2;
        }
    }

    uint32_t offA[2], offB[4];
#pragma unroll
    for (int mf = 0; mf < 2; mf++)
        offA[mf] = (uint32_t)((wm * 32 + mf * 16 + (lane & 7) + ((lane >> 3) & 1) * 8) * KS2
                              + ((lane >> 4) & 1) * 8);
#pragma unroll
    for (int p = 0; p < 4; p++)
        offB[p] = (uint32_t)((BM2 + wn * 64 + p * 16 + (lane & 7) + ((lane >> 4) & 1) * 8) * KS2
                             + ((lane >> 3) & 1) * 8);

    const int NIT = (IDIM / BK) / 2;  // 64 pair-iterations
#pragma unroll
    for (int s = 0; s < 2; s++) {
        uint32_t db = stg_b + s * G2_STGH * 2;
#pragma unroll
        for (int t = 0; t < 4; t++) cp16(db + dsto[t], srcb[t] + s * BK);
    }
    CP_COMMIT();

    float acc[2][8][4];
#pragma unroll
    for (int a = 0; a < 2; a++)
#pragma unroll
        for (int b = 0; b < 8; b++)
#pragma unroll
            for (int c = 0; c < 4; c++) acc[a][b][c] = 0.0f;

    for (int it = 0; it < NIT; it++) {
        CP_WAIT0();
        __syncthreads();
        if (it + 1 < NIT) {
            int pp = (it + 1) & 1;
#pragma unroll
            for (int s = 0; s < 2; s++) {
                uint32_t db = stg_b + (2 * pp + s) * G2_STGH * 2;
                int kslab = 2 * (it + 1) + s;
#pragma unroll
                for (int t = 0; t < 4; t++) cp16(db + dsto[t], srcb[t] + kslab * BK);
            }
            CP_COMMIT();
        }
        int cp = it & 1;
#pragma unroll
        for (int s = 0; s < 2; s++) {
            uint32_t stage_b = stg_b + (2 * cp + s) * G2_STGH * 2;
#pragma unroll
            for (int ks = 0; ks < 2; ks++) {
                uint32_t kb = stage_b + ks * 32;
                unsigned a[2][4], b[8][2];
                ldsm_x4(a[0], kb + offA[0] * 2);
                ldsm_x4(a[1], kb + offA[1] * 2);
                ldsm_x4(&b[0][0], kb + offB[0] * 2);
                ldsm_x4(&b[2][0], kb + offB[1] * 2);
                ldsm_x4(&b[4][0], kb + offB[2] * 2);
                ldsm_x4(&b[6][0], kb + offB[3] * 2);
#pragma unroll
                for (int mf = 0; mf < 2; mf++)
#pragma unroll
                    for (int nf = 0; nf < 8; nf++) mma_f16(acc[mf][nf], a[mf], b[nf]);
            }
        }
    }

    // epilogue: weighted scatter-add (exactly 2 adds per out element)
    int g4 = lane >> 2, tig = lane & 3;
#pragma unroll
    for (int mf = 0; mf < 2; mf++) {
#pragma unroll
        for (int half = 0; half < 2; half++) {
            int r = wm * 32 + mf * 16 + g4 + half * 8;
            int gr = m0 + r;
            if (gr < cnt) {
                int tok = g_tok[e * T_TOK + gr];
                float w = g_wt[e * T_TOK + gr];
                float* op = out + (size_t)tok * H + n0 + wn * 64;
#pragma unroll
                for (int nf = 0; nf < 8; nf++) {
                    atomicAdd(op + nf * 8 + tig * 2, w * acc[mf][nf][half * 2 + 0]);
                    atomicAdd(op + nf * 8 + tig * 2 + 1, w * acc[mf][nf][half * 2 + 1]);
                }
            }
        }
    }
}

// ---------------- launch ----------------
extern "C" void kernel_launch(void* const* d_in, const int* in_sizes, int n_in,
                              void* d_out, int out_size) {
    const float* x = (const float*)d_in[0];
    const float* gate_w = (const float*)d_in[1];
    const float* gate_up_w = (const float*)d_in[2];
    const float* down_w = (const float*)d_in[3];
    float* out = (float*)d_out;

    static int attr_done = 0;
    if (!attr_done) {
        cudaFuncSetAttribute(gemm1_kernel, cudaFuncAttributeMaxDynamicSharedMemorySize, G1_SMEM);
        cudaFuncSetAttribute(gemm2_kernel, cudaFuncAttributeMaxDynamicSharedMemorySize, G2_SMEM);
        attr_done = 1;
    }

    zero_out_kernel<<<4096, 256>>>(out, out_size);

    __half* xh_p;   cudaGetSymbolAddress((void**)&xh_p, g_xh);
    __half* w1h_p;  cudaGetSymbolAddress((void**)&w1h_p, g_w1h);
    __half* w2h_p;  cudaGetSymbolAddress((void**)&w2h_p, g_w2h);
    cvt_f2h_kernel<<<2048, 256>>>((const float4*)x, (uint2*)xh_p, (size_t)T_TOK * H / 4);
    cvt_f2h_kernel<<<8192, 256>>>((const float4*)gate_up_w, (uint2*)w1h_p,
                                  (size_t)NE * 2 * IDIM * H / 4);
    cvt_f2h_kernel<<<4096, 256>>>((const float4*)down_w, (uint2*)w2h_p,
                                  (size_t)NE * H * IDIM / 4);

    gating_kernel<<<T_TOK / 8, 256>>>(x, gate_w);
    scan_aux_kernel<<<1, 256>>>(out);

    dim3 g1(T_TOK / BM1, IDIM / BN1, NE);  // (64, 64, 8)
    gemm1_kernel<<<g1, 256, G1_SMEM>>>(xh_p, w1h_p);

    dim3 g2(T_TOK / BM2, H / BN2, NE);     // (64, 8, 8)
    gemm2_kernel<<<g2, 256, G2_SMEM>>>(w2h_p, out);
}